// round 5
// baseline (speedup 1.0000x reference)
#include <cuda_runtime.h>
#include <cuda_bf16.h>

#define HIDDEN   1024
#define NHEAD    16
#define HSZ      64
#define BATCH    2
#define SEQ      2048
#define MTOK     (BATCH * SEQ)         // 4096 token rows
#define QKV_F    (3 * HIDDEN)          // 3072

// Scratch (no cudaMalloc allowed): qkv activations + attention output
__device__ float g_qkv[MTOK * QKV_F];    // 48 MB
__device__ float g_attn[MTOK * HIDDEN];  // 16 MB

// ---------------------------------------------------------------------------
// Generic SGEMM + bias: C[M,N] = A[M,K] * B[K,N] + bias[N]
// 128x128 tile, BK=8, 256 threads, 8x8 per thread.
// Requires M%128==0, N%128==0, K%8==0 (true for all three calls).
// ---------------------------------------------------------------------------
__global__ __launch_bounds__(256) void sgemm_bias_kernel(
    const float* __restrict__ A, const float* __restrict__ B,
    const float* __restrict__ bias, float* __restrict__ C,
    int M, int N, int K)
{
    __shared__ float As[8][128];   // transposed A tile
    __shared__ float Bs[8][128];

    const int bx = blockIdx.x;     // N tile
    const int by = blockIdx.y;     // M tile
    const int tid = threadIdx.x;
    const int tx = tid & 15;       // 0..15 (col group)
    const int ty = tid >> 4;       // 0..15 (row group)

    const float* Aptr = A + (size_t)by * 128 * K;
    const float* Bptr = B + (size_t)bx * 128;

    const int a_row = tid >> 1;          // 0..127
    const int a_col = (tid & 1) * 4;     // 0 or 4
    const int b_row = tid >> 5;          // 0..7
    const int b_col = (tid & 31) * 4;    // 0..124

    float acc[8][8];
    #pragma unroll
    for (int i = 0; i < 8; i++)
        #pragma unroll
        for (int j = 0; j < 8; j++) acc[i][j] = 0.f;

    for (int k0 = 0; k0 < K; k0 += 8) {
        float4 av = *(const float4*)(Aptr + (size_t)a_row * K + k0 + a_col);
        float4 bv = *(const float4*)(Bptr + (size_t)(k0 + b_row) * N + b_col);
        As[a_col + 0][a_row] = av.x;
        As[a_col + 1][a_row] = av.y;
        As[a_col + 2][a_row] = av.z;
        As[a_col + 3][a_row] = av.w;
        *(float4*)&Bs[b_row][b_col] = bv;
        __syncthreads();

        #pragma unroll
        for (int kk = 0; kk < 8; kk++) {
            float ar[8], br[8];
            #pragma unroll
            for (int i = 0; i < 8; i++) ar[i] = As[kk][ty * 8 + i];
            #pragma unroll
            for (int j = 0; j < 8; j++) br[j] = Bs[kk][tx * 8 + j];
            #pragma unroll
            for (int i = 0; i < 8; i++)
                #pragma unroll
                for (int j = 0; j < 8; j++)
                    acc[i][j] += ar[i] * br[j];
        }
        __syncthreads();
    }

    // Epilogue: add bias, write out
    #pragma unroll
    for (int i = 0; i < 8; i++) {
        int row = by * 128 + ty * 8 + i;
        float* crow = C + (size_t)row * N + bx * 128;
        const float* brow = bias + bx * 128;
        #pragma unroll
        for (int j = 0; j < 8; j += 4) {
            int col = tx * 8 + j;
            float4 v;
            v.x = acc[i][j + 0] + brow[col + 0];
            v.y = acc[i][j + 1] + brow[col + 1];
            v.z = acc[i][j + 2] + brow[col + 2];
            v.w = acc[i][j + 3] + brow[col + 3];
            *(float4*)(crow + col) = v;
        }
    }
}

// ---------------------------------------------------------------------------
// Flash-attention style fused attention.
// Grid: (SEQ/64, NHEAD, BATCH), 256 threads.
// Each block: one 64-row Q tile of one (b, h). Iterates 64-row K/V tiles,
// online softmax, fp32 accumulators (4x4 fragment per thread).
// Dynamic smem: Qs[64][65] + Ks[64][65] + Vs[64][65] + Ps[64][65] = 66560 B.
// ---------------------------------------------------------------------------
#define ATT_SMEM (4 * 64 * 65 * 4)

__global__ __launch_bounds__(256) void attn_kernel(
    const float* __restrict__ qkv, float* __restrict__ attn_out)
{
    extern __shared__ float sm[];
    float (*Qs)[65] = (float(*)[65])(sm);
    float (*Ks)[65] = (float(*)[65])(sm + 64 * 65);
    float (*Vs)[65] = (float(*)[65])(sm + 2 * 64 * 65);
    float (*Ps)[65] = (float(*)[65])(sm + 3 * 64 * 65);

    const int q0 = blockIdx.x * 64;
    const int h  = blockIdx.y;
    const int b  = blockIdx.z;
    const int tid = threadIdx.x;
    const int tx = tid & 15;     // col group (4 cols)
    const int ty = tid >> 4;     // row group (4 rows)
    const float scale = 0.125f;  // 1/sqrt(64)

    const float* base = qkv + (size_t)b * SEQ * QKV_F;

    // Load Q tile: 64 rows x 64 d. 4 threads per row, 16 floats each.
    {
        int row = tid >> 2;
        int c0  = (tid & 3) * 16;
        const float* src = base + (size_t)(q0 + row) * QKV_F + h * HSZ + c0;
        #pragma unroll
        for (int u = 0; u < 4; u++) {
            float4 v = *(const float4*)(src + u * 4);
            Qs[row][c0 + u * 4 + 0] = v.x;
            Qs[row][c0 + u * 4 + 1] = v.y;
            Qs[row][c0 + u * 4 + 2] = v.z;
            Qs[row][c0 + u * 4 + 3] = v.w;
        }
    }

    float m_i[4], l_i[4], O[4][4];
    #pragma unroll
    for (int i = 0; i < 4; i++) {
        m_i[i] = -1e30f; l_i[i] = 0.f;
        #pragma unroll
        for (int c = 0; c < 4; c++) O[i][c] = 0.f;
    }
    __syncthreads();

    for (int k0 = 0; k0 < SEQ; k0 += 64) {
        // Load K and V tiles
        {
            int row = tid >> 2;
            int c0  = (tid & 3) * 16;
            const float* ksrc = base + (size_t)(k0 + row) * QKV_F + HIDDEN + h * HSZ + c0;
            const float* vsrc = ksrc + HIDDEN;
            #pragma unroll
            for (int u = 0; u < 4; u++) {
                float4 kv = *(const float4*)(ksrc + u * 4);
                Ks[row][c0 + u * 4 + 0] = kv.x;
                Ks[row][c0 + u * 4 + 1] = kv.y;
                Ks[row][c0 + u * 4 + 2] = kv.z;
                Ks[row][c0 + u * 4 + 3] = kv.w;
                float4 vv = *(const float4*)(vsrc + u * 4);
                Vs[row][c0 + u * 4 + 0] = vv.x;
                Vs[row][c0 + u * 4 + 1] = vv.y;
                Vs[row][c0 + u * 4 + 2] = vv.z;
                Vs[row][c0 + u * 4 + 3] = vv.w;
            }
        }
        __syncthreads();

        // S = scale * Q @ K^T  (4x4 fragment per thread)
        float s[4][4];
        #pragma unroll
        for (int i = 0; i < 4; i++)
            #pragma unroll
            for (int j = 0; j < 4; j++) s[i][j] = 0.f;

        for (int d = 0; d < 64; d++) {
            float qv[4], kv[4];
            #pragma unroll
            for (int i = 0; i < 4; i++) qv[i] = Qs[ty * 4 + i][d];
            #pragma unroll
            for (int j = 0; j < 4; j++) kv[j] = Ks[tx * 4 + j][d];
            #pragma unroll
            for (int i = 0; i < 4; i++)
                #pragma unroll
                for (int j = 0; j < 4; j++)
                    s[i][j] += qv[i] * kv[j];
        }
        #pragma unroll
        for (int i = 0; i < 4; i++)
            #pragma unroll
            for (int j = 0; j < 4; j++) s[i][j] *= scale;

        // Row max across the 16-lane tx group (lanes share ty)
        float rmax[4];
        #pragma unroll
        for (int i = 0; i < 4; i++) {
            float m = s[i][0];
            m = fmaxf(m, s[i][1]); m = fmaxf(m, s[i][2]); m = fmaxf(m, s[i][3]);
            #pragma unroll
            for (int off = 1; off < 16; off <<= 1)
                m = fmaxf(m, __shfl_xor_sync(0xffffffffu, m, off));
            rmax[i] = m;
        }

        // Online softmax update
        float corr[4], rsum[4];
        #pragma unroll
        for (int i = 0; i < 4; i++) {
            float m_new = fmaxf(m_i[i], rmax[i]);
            corr[i] = __expf(m_i[i] - m_new);
            m_i[i] = m_new;
            float acc = 0.f;
            #pragma unroll
            for (int j = 0; j < 4; j++) {
                float p = __expf(s[i][j] - m_new);
                Ps[ty * 4 + i][tx * 4 + j] = p;
                acc += p;
            }
            rsum[i] = acc;
        }
        #pragma unroll
        for (int i = 0; i < 4; i++) {
            float r = rsum[i];
            #pragma unroll
            for (int off = 1; off < 16; off <<= 1)
                r += __shfl_xor_sync(0xffffffffu, r, off);
            l_i[i] = l_i[i] * corr[i] + r;
            #pragma unroll
            for (int c = 0; c < 4; c++) O[i][c] *= corr[i];
        }
        __syncthreads();   // Ps visible to all

        // O += P @ V
        for (int j = 0; j < 64; j++) {
            float pv[4], vv[4];
            #pragma unroll
            for (int i = 0; i < 4; i++) pv[i] = Ps[ty * 4 + i][j];
            #pragma unroll
            for (int c = 0; c < 4; c++) vv[c] = Vs[j][tx * 4 + c];
            #pragma unroll
            for (int i = 0; i < 4; i++)
                #pragma unroll
                for (int c = 0; c < 4; c++)
                    O[i][c] += pv[i] * vv[c];
        }
        __syncthreads();   // before next tile overwrites Ks/Vs/Ps
    }

    // Epilogue: normalize, scatter to attn layout [tok, h*64+d]
    #pragma unroll
    for (int i = 0; i < 4; i++) {
        float inv = 1.f / l_i[i];
        int row = q0 + ty * 4 + i;
        float* dst = attn_out + ((size_t)(b * SEQ + row)) * HIDDEN + h * HSZ + tx * 4;
        float4 v;
        v.x = O[i][0] * inv; v.y = O[i][1] * inv;
        v.z = O[i][2] * inv; v.w = O[i][3] * inv;
        *(float4*)dst = v;
    }
}

// ---------------------------------------------------------------------------
extern "C" void kernel_launch(void* const* d_in, const int* in_sizes, int n_in,
                              void* d_out, int out_size)
{
    const float* x    = (const float*)d_in[0];
    const float* Wqkv = (const float*)d_in[1];
    const float* bqkv = (const float*)d_in[2];
    const float* Wo   = (const float*)d_in[3];
    const float* bo   = (const float*)d_in[4];
    float* out = (float*)d_out;

    float* qkv;  cudaGetSymbolAddress((void**)&qkv,  g_qkv);
    float* attn; cudaGetSymbolAddress((void**)&attn, g_attn);

    cudaFuncSetAttribute(attn_kernel,
                         cudaFuncAttributeMaxDynamicSharedMemorySize, ATT_SMEM);

    // 1) QKV projection: [4096,1024] @ [1024,3072] + bqkv
    {
        dim3 grid(QKV_F / 128, MTOK / 128);
        sgemm_bias_kernel<<<grid, 256>>>(x, Wqkv, bqkv, qkv, MTOK, QKV_F, HIDDEN);
    }
    // 2) Attention
    {
        dim3 grid(SEQ / 64, NHEAD, BATCH);
        attn_kernel<<<grid, 256, ATT_SMEM>>>(qkv, attn);
    }
    // 3) Output projection: [4096,1024] @ [1024,1024] + bo
    {
        dim3 grid(HIDDEN / 128, MTOK / 128);
        sgemm_bias_kernel<<<grid, 256>>>(attn, Wo, bo, out, MTOK, HIDDEN, HIDDEN);
    }
}

// round 8
// speedup vs baseline: 1.3399x; 1.3399x over previous
#include <cuda_runtime.h>
#include <cuda_bf16.h>
#include <cstdint>

#define HIDDEN   1024
#define NHEAD    16
#define HSZ      64
#define BATCH    2
#define SEQ      2048
#define MTOK     (BATCH * SEQ)         // 4096 token rows
#define QKV_F    (3 * HIDDEN)          // 3072

// ---------------------------------------------------------------------------
// Scratch (no cudaMalloc allowed)
// ---------------------------------------------------------------------------
__device__ float g_qkv[MTOK * QKV_F];    // 48 MB fp32 qkv activations
__device__ float g_attn[MTOK * HIDDEN];  // 16 MB fp32 attention output
__device__ __nv_bfloat16 g_xhi[MTOK * HIDDEN];
__device__ __nv_bfloat16 g_xlo[MTOK * HIDDEN];
__device__ __nv_bfloat16 g_wqt_hi[QKV_F * HIDDEN];   // Wqkv^T [3072,1024]
__device__ __nv_bfloat16 g_wqt_lo[QKV_F * HIDDEN];
__device__ __nv_bfloat16 g_wot_hi[HIDDEN * HIDDEN];  // Wo^T [1024,1024]
__device__ __nv_bfloat16 g_wot_lo[HIDDEN * HIDDEN];
__device__ __nv_bfloat16 g_ahi[MTOK * HIDDEN];
__device__ __nv_bfloat16 g_alo[MTOK * HIDDEN];

// ---------------------------------------------------------------------------
// mma.sync / ldmatrix helpers (sm_80+ ISA; valid on base sm_103 target)
// ---------------------------------------------------------------------------
__device__ __forceinline__ void ldsm_x4(uint32_t* r, uint32_t addr) {
    asm volatile("ldmatrix.sync.aligned.m8n8.x4.shared.b16 {%0,%1,%2,%3}, [%4];"
                 : "=r"(r[0]), "=r"(r[1]), "=r"(r[2]), "=r"(r[3]) : "r"(addr));
}
__device__ __forceinline__ void ldsm_x2(uint32_t* r, uint32_t addr) {
    asm volatile("ldmatrix.sync.aligned.m8n8.x2.shared.b16 {%0,%1}, [%2];"
                 : "=r"(r[0]), "=r"(r[1]) : "r"(addr));
}
__device__ __forceinline__ void mma_bf16(float* c, const uint32_t* a, const uint32_t* b) {
    asm volatile(
        "mma.sync.aligned.m16n8k16.row.col.f32.bf16.bf16.f32 "
        "{%0,%1,%2,%3}, {%4,%5,%6,%7}, {%8,%9}, {%0,%1,%2,%3};"
        : "+f"(c[0]), "+f"(c[1]), "+f"(c[2]), "+f"(c[3])
        : "r"(a[0]), "r"(a[1]), "r"(a[2]), "r"(a[3]), "r"(b[0]), "r"(b[1]));
}

// ---------------------------------------------------------------------------
// fp32 -> bf16 hi/lo split (elementwise, float4 vectorized)
// ---------------------------------------------------------------------------
__global__ __launch_bounds__(256) void f32_split_kernel(
    const float* __restrict__ in, __nv_bfloat16* __restrict__ hi,
    __nv_bfloat16* __restrict__ lo, int n)
{
    int i = (blockIdx.x * 256 + threadIdx.x) * 4;
    if (i >= n) return;
    float4 v = *(const float4*)(in + i);
    __nv_bfloat16 h0 = __float2bfloat16(v.x);
    __nv_bfloat16 h1 = __float2bfloat16(v.y);
    __nv_bfloat16 h2 = __float2bfloat16(v.z);
    __nv_bfloat16 h3 = __float2bfloat16(v.w);
    __nv_bfloat16 l0 = __float2bfloat16(v.x - __bfloat162float(h0));
    __nv_bfloat16 l1 = __float2bfloat16(v.y - __bfloat162float(h1));
    __nv_bfloat16 l2 = __float2bfloat16(v.z - __bfloat162float(h2));
    __nv_bfloat16 l3 = __float2bfloat16(v.w - __bfloat162float(h3));
    *(__nv_bfloat162*)(hi + i)     = __nv_bfloat162(h0, h1);
    *(__nv_bfloat162*)(hi + i + 2) = __nv_bfloat162(h2, h3);
    *(__nv_bfloat162*)(lo + i)     = __nv_bfloat162(l0, l1);
    *(__nv_bfloat162*)(lo + i + 2) = __nv_bfloat162(l2, l3);
}

// ---------------------------------------------------------------------------
// Transpose W[K,N] fp32 -> T_hi/T_lo[N,K] bf16 split. block (32,8), tile 32x32.
// ---------------------------------------------------------------------------
__global__ __launch_bounds__(256) void transpose_split_kernel(
    const float* __restrict__ W, __nv_bfloat16* __restrict__ Thi,
    __nv_bfloat16* __restrict__ Tlo, int K, int N)
{
    __shared__ float t[32][33];
    int n = blockIdx.x * 32 + threadIdx.x;
    int k0 = blockIdx.y * 32;
    #pragma unroll
    for (int i = threadIdx.y; i < 32; i += 8)
        t[i][threadIdx.x] = W[(size_t)(k0 + i) * N + n];
    __syncthreads();
    int k = k0 + threadIdx.x;
    int nb = blockIdx.x * 32;
    #pragma unroll
    for (int i = threadIdx.y; i < 32; i += 8) {
        float v = t[threadIdx.x][i];
        __nv_bfloat16 h = __float2bfloat16(v);
        Thi[(size_t)(nb + i) * K + k] = h;
        Tlo[(size_t)(nb + i) * K + k] = __float2bfloat16(v - __bfloat162float(h));
    }
}

// ---------------------------------------------------------------------------
// HMMA GEMM, 2-term bf16 split (3 products): C = A*B^T + bias
//  A hi/lo [M,K] bf16 K-major; B hi/lo [N,K] bf16 K-major; C [M,N] fp32.
//  128x128 tile, BK=32, 256 threads (8 warps, each 64x32 via 2x4 warp grid).
//  Smem rows padded to 40 bf16 (80B) -> conflict-free ldmatrix.
// ---------------------------------------------------------------------------
#define GPAD 40

__global__ __launch_bounds__(256) void gemm_mma_kernel(
    const __nv_bfloat16* __restrict__ Ahi, const __nv_bfloat16* __restrict__ Alo,
    const __nv_bfloat16* __restrict__ Bhi, const __nv_bfloat16* __restrict__ Blo,
    const float* __restrict__ bias, float* __restrict__ C,
    int M, int N, int K)
{
    __shared__ __nv_bfloat16 sAh[128][GPAD];
    __shared__ __nv_bfloat16 sAl[128][GPAD];
    __shared__ __nv_bfloat16 sBh[128][GPAD];
    __shared__ __nv_bfloat16 sBl[128][GPAD];

    const int tid  = threadIdx.x;
    const int wid  = tid >> 5;
    const int lane = tid & 31;
    const int warp_m = (wid & 1) * 64;    // 0 or 64
    const int warp_n = (wid >> 1) * 32;   // 0,32,64,96
    const int m0 = blockIdx.y * 128;
    const int n0 = blockIdx.x * 128;

    float acc[4][4][4];
    #pragma unroll
    for (int i = 0; i < 4; i++)
        #pragma unroll
        for (int j = 0; j < 4; j++)
            #pragma unroll
            for (int c = 0; c < 4; c++) acc[i][j][c] = 0.f;

    // ldmatrix lane addressing
    const int a_r = lane & 15;             // row within 16-row tile
    const int a_c = (lane >> 4) * 8;       // k offset 0/8
    const int b_r = lane & 7;              // row within 8-row tile
    const int b_c = ((lane >> 3) & 1) * 8; // k offset 0/8 (lanes 0-15 used)

    for (int k0 = 0; k0 < K; k0 += 32) {
        // Load 4 matrices of [128 x 32] bf16 = 512 x 16B chunks each.
        #pragma unroll
        for (int i0 = 0; i0 < 512; i0 += 256) {
            int i = i0 + tid;
            int r = i >> 2;
            int c = (i & 3) * 8;
            size_t ga = (size_t)(m0 + r) * K + k0 + c;
            size_t gb = (size_t)(n0 + r) * K + k0 + c;
            *(uint4*)&sAh[r][c] = *(const uint4*)(Ahi + ga);
            *(uint4*)&sAl[r][c] = *(const uint4*)(Alo + ga);
            *(uint4*)&sBh[r][c] = *(const uint4*)(Bhi + gb);
            *(uint4*)&sBl[r][c] = *(const uint4*)(Blo + gb);
        }
        __syncthreads();

        #pragma unroll
        for (int ks = 0; ks < 2; ks++) {
            const int kb = ks * 16;
            uint32_t ah[4][4], al[4][4], bh[4][2], bl[4][2];
            #pragma unroll
            for (int mt = 0; mt < 4; mt++) {
                int row = warp_m + mt * 16 + a_r;
                ldsm_x4(ah[mt], (uint32_t)__cvta_generic_to_shared(&sAh[row][kb + a_c]));
                ldsm_x4(al[mt], (uint32_t)__cvta_generic_to_shared(&sAl[row][kb + a_c]));
            }
            #pragma unroll
            for (int nt = 0; nt < 4; nt++) {
                int row = warp_n + nt * 8 + b_r;
                ldsm_x2(bh[nt], (uint32_t)__cvta_generic_to_shared(&sBh[row][kb + b_c]));
                ldsm_x2(bl[nt], (uint32_t)__cvta_generic_to_shared(&sBl[row][kb + b_c]));
            }
            #pragma unroll
            for (int mt = 0; mt < 4; mt++)
                #pragma unroll
                for (int nt = 0; nt < 4; nt++) {
                    mma_bf16(acc[mt][nt], ah[mt], bh[nt]);
                    mma_bf16(acc[mt][nt], ah[mt], bl[nt]);
                    mma_bf16(acc[mt][nt], al[mt], bh[nt]);
                }
        }
        __syncthreads();
    }

    // Epilogue: c0,c1 -> row g, cols q*2, q*2+1; c2,c3 -> row g+8.
    const int g = lane >> 2;
    const int q = (lane & 3) * 2;
    #pragma unroll
    for (int mt = 0; mt < 4; mt++) {
        #pragma unroll
        for (int nt = 0; nt < 4; nt++) {
            int row = m0 + warp_m + mt * 16 + g;
            int col = n0 + warp_n + nt * 8 + q;
            float b0 = bias[col], b1 = bias[col + 1];
            float* p0 = C + (size_t)row * N + col;
            p0[0] = acc[mt][nt][0] + b0;
            p0[1] = acc[mt][nt][1] + b1;
            float* p1 = C + (size_t)(row + 8) * N + col;
            p1[0] = acc[mt][nt][2] + b0;
            p1[1] = acc[mt][nt][3] + b1;
        }
    }
}

// ---------------------------------------------------------------------------
// Flash-attention style fused attention (fp32 scalar, unchanged).
// ---------------------------------------------------------------------------
#define ATT_SMEM (4 * 64 * 65 * 4)

__global__ __launch_bounds__(256) void attn_kernel(
    const float* __restrict__ qkv, float* __restrict__ attn_out)
{
    extern __shared__ float sm[];
    float (*Qs)[65] = (float(*)[65])(sm);
    float (*Ks)[65] = (float(*)[65])(sm + 64 * 65);
    float (*Vs)[65] = (float(*)[65])(sm + 2 * 64 * 65);
    float (*Ps)[65] = (float(*)[65])(sm + 3 * 64 * 65);

    const int q0 = blockIdx.x * 64;
    const int h  = blockIdx.y;
    const int b  = blockIdx.z;
    const int tid = threadIdx.x;
    const int tx = tid & 15;
    const int ty = tid >> 4;
    const float scale = 0.125f;

    const float* base = qkv + (size_t)b * SEQ * QKV_F;

    {
        int row = tid >> 2;
        int c0  = (tid & 3) * 16;
        const float* src = base + (size_t)(q0 + row) * QKV_F + h * HSZ + c0;
        #pragma unroll
        for (int u = 0; u < 4; u++) {
            float4 v = *(const float4*)(src + u * 4);
            Qs[row][c0 + u * 4 + 0] = v.x;
            Qs[row][c0 + u * 4 + 1] = v.y;
            Qs[row][c0 + u * 4 + 2] = v.z;
            Qs[row][c0 + u * 4 + 3] = v.w;
        }
    }

    float m_i[4], l_i[4], O[4][4];
    #pragma unroll
    for (int i = 0; i < 4; i++) {
        m_i[i] = -1e30f; l_i[i] = 0.f;
        #pragma unroll
        for (int c = 0; c < 4; c++) O[i][c] = 0.f;
    }
    __syncthreads();

    for (int k0 = 0; k0 < SEQ; k0 += 64) {
        {
            int row = tid >> 2;
            int c0  = (tid & 3) * 16;
            const float* ksrc = base + (size_t)(k0 + row) * QKV_F + HIDDEN + h * HSZ + c0;
            const float* vsrc = ksrc + HIDDEN;
            #pragma unroll
            for (int u = 0; u < 4; u++) {
                float4 kv = *(const float4*)(ksrc + u * 4);
                Ks[row][c0 + u * 4 + 0] = kv.x;
                Ks[row][c0 + u * 4 + 1] = kv.y;
                Ks[row][c0 + u * 4 + 2] = kv.z;
                Ks[row][c0 + u * 4 + 3] = kv.w;
                float4 vv = *(const float4*)(vsrc + u * 4);
                Vs[row][c0 + u * 4 + 0] = vv.x;
                Vs[row][c0 + u * 4 + 1] = vv.y;
                Vs[row][c0 + u * 4 + 2] = vv.z;
                Vs[row][c0 + u * 4 + 3] = vv.w;
            }
        }
        __syncthreads();

        float s[4][4];
        #pragma unroll
        for (int i = 0; i < 4; i++)
            #pragma unroll
            for (int j = 0; j < 4; j++) s[i][j] = 0.f;

        for (int d = 0; d < 64; d++) {
            float qv[4], kv[4];
            #pragma unroll
            for (int i = 0; i < 4; i++) qv[i] = Qs[ty * 4 + i][d];
            #pragma unroll
            for (int j = 0; j < 4; j++) kv[j] = Ks[tx * 4 + j][d];
            #pragma unroll
            for (int i = 0; i < 4; i++)
                #pragma unroll
                for (int j = 0; j < 4; j++)
                    s[i][j] += qv[i] * kv[j];
        }
        #pragma unroll
        for (int i = 0; i < 4; i++)
            #pragma unroll
            for (int j = 0; j < 4; j++) s[i][j] *= scale;

        float rmax[4];
        #pragma unroll
        for (int i = 0; i < 4; i++) {
            float m = s[i][0];
            m = fmaxf(m, s[i][1]); m = fmaxf(m, s[i][2]); m = fmaxf(m, s[i][3]);
            #pragma unroll
            for (int off = 1; off < 16; off <<= 1)
                m = fmaxf(m, __shfl_xor_sync(0xffffffffu, m, off));
            rmax[i] = m;
        }

        float corr[4], rsum[4];
        #pragma unroll
        for (int i = 0; i < 4; i++) {
            float m_new = fmaxf(m_i[i], rmax[i]);
            corr[i] = __expf(m_i[i] - m_new);
            m_i[i] = m_new;
            float acc = 0.f;
            #pragma unroll
            for (int j = 0; j < 4; j++) {
                float p = __expf(s[i][j] - m_new);
                Ps[ty * 4 + i][tx * 4 + j] = p;
                acc += p;
            }
            rsum[i] = acc;
        }
        #pragma unroll
        for (int i = 0; i < 4; i++) {
            float r = rsum[i];
            #pragma unroll
            for (int off = 1; off < 16; off <<= 1)
                r += __shfl_xor_sync(0xffffffffu, r, off);
            l_i[i] = l_i[i] * corr[i] + r;
            #pragma unroll
            for (int c = 0; c < 4; c++) O[i][c] *= corr[i];
        }
        __syncthreads();

        for (int j = 0; j < 64; j++) {
            float pv[4], vv[4];
            #pragma unroll
            for (int i = 0; i < 4; i++) pv[i] = Ps[ty * 4 + i][j];
            #pragma unroll
            for (int c = 0; c < 4; c++) vv[c] = Vs[j][tx * 4 + c];
            #pragma unroll
            for (int i = 0; i < 4; i++)
                #pragma unroll
                for (int c = 0; c < 4; c++)
                    O[i][c] += pv[i] * vv[c];
        }
        __syncthreads();
    }

    #pragma unroll
    for (int i = 0; i < 4; i++) {
        float inv = 1.f / l_i[i];
        int row = q0 + ty * 4 + i;
        float* dst = attn_out + ((size_t)(b * SEQ + row)) * HIDDEN + h * HSZ + tx * 4;
        float4 v;
        v.x = O[i][0] * inv; v.y = O[i][1] * inv;
        v.z = O[i][2] * inv; v.w = O[i][3] * inv;
        *(float4*)dst = v;
    }
}

// ---------------------------------------------------------------------------
extern "C" void kernel_launch(void* const* d_in, const int* in_sizes, int n_in,
                              void* d_out, int out_size)
{
    const float* x    = (const float*)d_in[0];
    const float* Wqkv = (const float*)d_in[1];
    const float* bqkv = (const float*)d_in[2];
    const float* Wo   = (const float*)d_in[3];
    const float* bo   = (const float*)d_in[4];
    float* out = (float*)d_out;

    float *qkv, *attn;
    __nv_bfloat16 *xhi, *xlo, *wqh, *wql, *woh, *wol, *ahi, *alo;
    cudaGetSymbolAddress((void**)&qkv,  g_qkv);
    cudaGetSymbolAddress((void**)&attn, g_attn);
    cudaGetSymbolAddress((void**)&xhi,  g_xhi);
    cudaGetSymbolAddress((void**)&xlo,  g_xlo);
    cudaGetSymbolAddress((void**)&wqh,  g_wqt_hi);
    cudaGetSymbolAddress((void**)&wql,  g_wqt_lo);
    cudaGetSymbolAddress((void**)&woh,  g_wot_hi);
    cudaGetSymbolAddress((void**)&wol,  g_wot_lo);
    cudaGetSymbolAddress((void**)&ahi,  g_ahi);
    cudaGetSymbolAddress((void**)&alo,  g_alo);

    cudaFuncSetAttribute(attn_kernel,
                         cudaFuncAttributeMaxDynamicSharedMemorySize, ATT_SMEM);

    // 0) Convert inputs to bf16 hi/lo (x elementwise, W transposed to [N,K])
    {
        int n = MTOK * HIDDEN;
        f32_split_kernel<<<n / 4 / 256, 256>>>(x, xhi, xlo, n);
        transpose_split_kernel<<<dim3(QKV_F / 32, HIDDEN / 32), dim3(32, 8)>>>(
            Wqkv, wqh, wql, HIDDEN, QKV_F);
        transpose_split_kernel<<<dim3(HIDDEN / 32, HIDDEN / 32), dim3(32, 8)>>>(
            Wo, woh, wol, HIDDEN, HIDDEN);
    }
    // 1) QKV projection on HMMA: qkv = x @ Wqkv + bqkv
    {
        dim3 grid(QKV_F / 128, MTOK / 128);
        gemm_mma_kernel<<<grid, 256>>>(xhi, xlo, wqh, wql, bqkv, qkv,
                                       MTOK, QKV_F, HIDDEN);
    }
    // 2) Attention (fp32 scalar)
    {
        dim3 grid(SEQ / 64, NHEAD, BATCH);
        attn_kernel<<<grid, 256, ATT_SMEM>>>(qkv, attn);
    }
    // 3) Convert attention output, then output projection on HMMA
    {
        int n = MTOK * HIDDEN;
        f32_split_kernel<<<n / 4 / 256, 256>>>(attn, ahi, alo, n);
        dim3 grid(HIDDEN / 128, MTOK / 128);
        gemm_mma_kernel<<<grid, 256>>>(ahi, alo, woh, wol, bo, out,
                                       MTOK, HIDDEN, HIDDEN);
    }
}

// round 9
// speedup vs baseline: 3.0247x; 2.2574x over previous
#include <cuda_runtime.h>
#include <cuda_bf16.h>
#include <cstdint>

#define HIDDEN   1024
#define NHEAD    16
#define HSZ      64
#define BATCH    2
#define SEQ      2048
#define MTOK     (BATCH * SEQ)         // 4096 token rows
#define QKV_F    (3 * HIDDEN)          // 3072

// ---------------------------------------------------------------------------
// Scratch (no cudaMalloc allowed)
// ---------------------------------------------------------------------------
__device__ __nv_bfloat16 g_xhi[MTOK * HIDDEN];
__device__ __nv_bfloat16 g_xlo[MTOK * HIDDEN];
__device__ __nv_bfloat16 g_wqt_hi[QKV_F * HIDDEN];   // Wqkv^T [3072,1024]
__device__ __nv_bfloat16 g_wqt_lo[QKV_F * HIDDEN];
__device__ __nv_bfloat16 g_wot_hi[HIDDEN * HIDDEN];  // Wo^T [1024,1024]
__device__ __nv_bfloat16 g_wot_lo[HIDDEN * HIDDEN];
__device__ __nv_bfloat16 g_qkvh[MTOK * QKV_F];       // qkv hi (Q pre-scaled)
__device__ __nv_bfloat16 g_qkvl[MTOK * QKV_F];       // qkv lo
__device__ __nv_bfloat16 g_ahi[MTOK * HIDDEN];       // attn out hi
__device__ __nv_bfloat16 g_alo[MTOK * HIDDEN];       // attn out lo

// ---------------------------------------------------------------------------
// mma.sync / ldmatrix helpers (sm_80+ ISA; valid on base sm_103 target)
// ---------------------------------------------------------------------------
__device__ __forceinline__ void ldsm_x4(uint32_t* r, uint32_t addr) {
    asm volatile("ldmatrix.sync.aligned.m8n8.x4.shared.b16 {%0,%1,%2,%3}, [%4];"
                 : "=r"(r[0]), "=r"(r[1]), "=r"(r[2]), "=r"(r[3]) : "r"(addr));
}
__device__ __forceinline__ void ldsm_x4_t(uint32_t* r, uint32_t addr) {
    asm volatile("ldmatrix.sync.aligned.m8n8.x4.trans.shared.b16 {%0,%1,%2,%3}, [%4];"
                 : "=r"(r[0]), "=r"(r[1]), "=r"(r[2]), "=r"(r[3]) : "r"(addr));
}
__device__ __forceinline__ void ldsm_x2(uint32_t* r, uint32_t addr) {
    asm volatile("ldmatrix.sync.aligned.m8n8.x2.shared.b16 {%0,%1}, [%2];"
                 : "=r"(r[0]), "=r"(r[1]) : "r"(addr));
}
__device__ __forceinline__ void mma_bf16(float* c, const uint32_t* a, const uint32_t* b) {
    asm volatile(
        "mma.sync.aligned.m16n8k16.row.col.f32.bf16.bf16.f32 "
        "{%0,%1,%2,%3}, {%4,%5,%6,%7}, {%8,%9}, {%0,%1,%2,%3};"
        : "+f"(c[0]), "+f"(c[1]), "+f"(c[2]), "+f"(c[3])
        : "r"(a[0]), "r"(a[1]), "r"(a[2]), "r"(a[3]), "r"(b[0]), "r"(b[1]));
}
__device__ __forceinline__ uint32_t smaddr(const void* p) {
    return (uint32_t)__cvta_generic_to_shared(p);
}
// split a pair of fp32 into bf16x2 hi and lo planes
__device__ __forceinline__ void split2(float a, float b,
                                       __nv_bfloat162& hi, __nv_bfloat162& lo) {
    __nv_bfloat16 ha = __float2bfloat16(a), hb = __float2bfloat16(b);
    hi = __nv_bfloat162(ha, hb);
    lo = __nv_bfloat162(__float2bfloat16(a - __bfloat162float(ha)),
                        __float2bfloat16(b - __bfloat162float(hb)));
}

// ---------------------------------------------------------------------------
// fp32 -> bf16 hi/lo split (elementwise, float4 vectorized)
// ---------------------------------------------------------------------------
__global__ __launch_bounds__(256) void f32_split_kernel(
    const float* __restrict__ in, __nv_bfloat16* __restrict__ hi,
    __nv_bfloat16* __restrict__ lo, int n)
{
    int i = (blockIdx.x * 256 + threadIdx.x) * 4;
    if (i >= n) return;
    float4 v = *(const float4*)(in + i);
    __nv_bfloat162 h01, l01, h23, l23;
    split2(v.x, v.y, h01, l01);
    split2(v.z, v.w, h23, l23);
    *(__nv_bfloat162*)(hi + i)     = h01;
    *(__nv_bfloat162*)(hi + i + 2) = h23;
    *(__nv_bfloat162*)(lo + i)     = l01;
    *(__nv_bfloat162*)(lo + i + 2) = l23;
}

// ---------------------------------------------------------------------------
// Transpose W[K,N] fp32 -> T_hi/T_lo[N,K] bf16 split. block (32,8), tile 32x32.
// ---------------------------------------------------------------------------
__global__ __launch_bounds__(256) void transpose_split_kernel(
    const float* __restrict__ W, __nv_bfloat16* __restrict__ Thi,
    __nv_bfloat16* __restrict__ Tlo, int K, int N)
{
    __shared__ float t[32][33];
    int n = blockIdx.x * 32 + threadIdx.x;
    int k0 = blockIdx.y * 32;
    #pragma unroll
    for (int i = threadIdx.y; i < 32; i += 8)
        t[i][threadIdx.x] = W[(size_t)(k0 + i) * N + n];
    __syncthreads();
    int k = k0 + threadIdx.x;
    int nb = blockIdx.x * 32;
    #pragma unroll
    for (int i = threadIdx.y; i < 32; i += 8) {
        float v = t[threadIdx.x][i];
        __nv_bfloat16 h = __float2bfloat16(v);
        Thi[(size_t)(nb + i) * K + k] = h;
        Tlo[(size_t)(nb + i) * K + k] = __float2bfloat16(v - __bfloat162float(h));
    }
}

// ---------------------------------------------------------------------------
// HMMA GEMM mainloop shared by both epilogues (macro-free: two kernels).
// 128x128 tile, BK=32, 256 threads (8 warps in 2x4 grid, each 64x32).
// ---------------------------------------------------------------------------
#define GPAD 40

#define GEMM_MAINLOOP                                                          \
    __shared__ __nv_bfloat16 sAh[128][GPAD];                                   \
    __shared__ __nv_bfloat16 sAl[128][GPAD];                                   \
    __shared__ __nv_bfloat16 sBh[128][GPAD];                                   \
    __shared__ __nv_bfloat16 sBl[128][GPAD];                                   \
    const int tid  = threadIdx.x;                                              \
    const int wid  = tid >> 5;                                                 \
    const int lane = tid & 31;                                                 \
    const int warp_m = (wid & 1) * 64;                                         \
    const int warp_n = (wid >> 1) * 32;                                        \
    const int m0 = blockIdx.y * 128;                                           \
    const int n0 = blockIdx.x * 128;                                           \
    float acc[4][4][4];                                                        \
    _Pragma("unroll")                                                          \
    for (int i = 0; i < 4; i++)                                                \
        _Pragma("unroll")                                                      \
        for (int j2 = 0; j2 < 4; j2++)                                         \
            _Pragma("unroll")                                                  \
            for (int c = 0; c < 4; c++) acc[i][j2][c] = 0.f;                   \
    const int a_r = lane & 15;                                                 \
    const int a_c = (lane >> 4) * 8;                                           \
    const int b_r = lane & 7;                                                  \
    const int b_c = ((lane >> 3) & 1) * 8;                                     \
    for (int k0 = 0; k0 < K; k0 += 32) {                                       \
        _Pragma("unroll")                                                      \
        for (int i0 = 0; i0 < 512; i0 += 256) {                                \
            int i = i0 + tid;                                                  \
            int r = i >> 2;                                                    \
            int c = (i & 3) * 8;                                               \
            size_t ga = (size_t)(m0 + r) * K + k0 + c;                         \
            size_t gb = (size_t)(n0 + r) * K + k0 + c;                         \
            *(uint4*)&sAh[r][c] = *(const uint4*)(Ahi + ga);                   \
            *(uint4*)&sAl[r][c] = *(const uint4*)(Alo + ga);                   \
            *(uint4*)&sBh[r][c] = *(const uint4*)(Bhi + gb);                   \
            *(uint4*)&sBl[r][c] = *(const uint4*)(Blo + gb);                   \
        }                                                                      \
        __syncthreads();                                                       \
        _Pragma("unroll")                                                      \
        for (int ks = 0; ks < 2; ks++) {                                       \
            const int kb = ks * 16;                                            \
            uint32_t ah[4][4], al[4][4], bh[4][2], bl[4][2];                   \
            _Pragma("unroll")                                                  \
            for (int mt = 0; mt < 4; mt++) {                                   \
                int row = warp_m + mt * 16 + a_r;                              \
                ldsm_x4(ah[mt], smaddr(&sAh[row][kb + a_c]));                  \
                ldsm_x4(al[mt], smaddr(&sAl[row][kb + a_c]));                  \
            }                                                                  \
            _Pragma("unroll")                                                  \
            for (int nt = 0; nt < 4; nt++) {                                   \
                int row = warp_n + nt * 8 + b_r;                               \
                ldsm_x2(bh[nt], smaddr(&sBh[row][kb + b_c]));                  \
                ldsm_x2(bl[nt], smaddr(&sBl[row][kb + b_c]));                  \
            }                                                                  \
            _Pragma("unroll")                                                  \
            for (int mt = 0; mt < 4; mt++)                                     \
                _Pragma("unroll")                                              \
                for (int nt = 0; nt < 4; nt++) {                               \
                    mma_bf16(acc[mt][nt], ah[mt], bh[nt]);                     \
                    mma_bf16(acc[mt][nt], ah[mt], bl[nt]);                     \
                    mma_bf16(acc[mt][nt], al[mt], bh[nt]);                     \
                }                                                              \
        }                                                                      \
        __syncthreads();                                                       \
    }                                                                          \
    const int g = lane >> 2;                                                   \
    const int q = (lane & 3) * 2;

// GEMM variant 1: fp32 output + bias (final projection)
__global__ __launch_bounds__(256) void gemm_mma_f32_kernel(
    const __nv_bfloat16* __restrict__ Ahi, const __nv_bfloat16* __restrict__ Alo,
    const __nv_bfloat16* __restrict__ Bhi, const __nv_bfloat16* __restrict__ Blo,
    const float* __restrict__ bias, float* __restrict__ C,
    int M, int N, int K)
{
    GEMM_MAINLOOP
    #pragma unroll
    for (int mt = 0; mt < 4; mt++) {
        #pragma unroll
        for (int nt = 0; nt < 4; nt++) {
            int row = m0 + warp_m + mt * 16 + g;
            int col = n0 + warp_n + nt * 8 + q;
            float b0 = bias[col], b1 = bias[col + 1];
            float* p0 = C + (size_t)row * N + col;
            p0[0] = acc[mt][nt][0] + b0;
            p0[1] = acc[mt][nt][1] + b1;
            float* p1 = C + (size_t)(row + 8) * N + col;
            p1[0] = acc[mt][nt][2] + b0;
            p1[1] = acc[mt][nt][3] + b1;
        }
    }
}

// GEMM variant 2: bf16 hi/lo output + bias, cols < qcols scaled (QKV projection)
__global__ __launch_bounds__(256) void gemm_mma_bf16out_kernel(
    const __nv_bfloat16* __restrict__ Ahi, const __nv_bfloat16* __restrict__ Alo,
    const __nv_bfloat16* __restrict__ Bhi, const __nv_bfloat16* __restrict__ Blo,
    const float* __restrict__ bias,
    __nv_bfloat16* __restrict__ Chi, __nv_bfloat16* __restrict__ Clo,
    int M, int N, int K, int qcols, float qscale)
{
    GEMM_MAINLOOP
    #pragma unroll
    for (int mt = 0; mt < 4; mt++) {
        #pragma unroll
        for (int nt = 0; nt < 4; nt++) {
            int row = m0 + warp_m + mt * 16 + g;
            int col = n0 + warp_n + nt * 8 + q;
            float b0 = bias[col], b1 = bias[col + 1];
            float v00 = acc[mt][nt][0] + b0, v01 = acc[mt][nt][1] + b1;
            float v10 = acc[mt][nt][2] + b0, v11 = acc[mt][nt][3] + b1;
            if (col < qcols) { v00 *= qscale; v01 *= qscale; v10 *= qscale; v11 *= qscale; }
            __nv_bfloat162 h, l;
            split2(v00, v01, h, l);
            *(__nv_bfloat162*)(Chi + (size_t)row * N + col) = h;
            *(__nv_bfloat162*)(Clo + (size_t)row * N + col) = l;
            split2(v10, v11, h, l);
            *(__nv_bfloat162*)(Chi + (size_t)(row + 8) * N + col) = h;
            *(__nv_bfloat162*)(Clo + (size_t)(row + 8) * N + col) = l;
        }
    }
}

// ---------------------------------------------------------------------------
// Flash attention on HMMA with hi/lo splits.
// Grid (SEQ/64, NHEAD, BATCH), 128 threads (4 warps x m16 rows).
// K/V tiles in swizzled smem (128B rows, granule XOR swizzle); Q frags and P
// stay in registers. Outputs bf16 hi/lo for the final projection.
// ---------------------------------------------------------------------------
__device__ __forceinline__ int swz(int row, int gran) {
    return row * 64 + ((gran ^ (row & 7)) << 3);   // bf16 element offset
}

__global__ __launch_bounds__(128, 3) void attn_mma_kernel(
    const __nv_bfloat16* __restrict__ qhi, const __nv_bfloat16* __restrict__ qlo,
    __nv_bfloat16* __restrict__ ohi, __nv_bfloat16* __restrict__ olo)
{
    // planes: 0=Khi 1=Klo 2=Vhi 3=Vlo  (Q uses 0/1 transiently at start)
    __shared__ __nv_bfloat16 sp[4][64 * 64];

    const int tid  = threadIdx.x;
    const int wid  = tid >> 5;
    const int lane = tid & 31;
    const int g = lane >> 2, j = lane & 3;
    const int q0 = blockIdx.x * 64;
    const int h  = blockIdx.y;
    const int b  = blockIdx.z;
    const int warp_m = wid * 16;

    const __nv_bfloat16* bqh = qhi + (size_t)b * SEQ * QKV_F;
    const __nv_bfloat16* bql = qlo + (size_t)b * SEQ * QKV_F;

    // ---- load Q tile (hi/lo) into planes 0/1, pull fragments to registers ----
    #pragma unroll
    for (int i = 0; i < 8; i++) {
        int idx = i * 128 + tid;          // 0..1023
        int pl = idx >> 9;
        int rem = idx & 511;
        int row = rem >> 3, gr = rem & 7;
        const __nv_bfloat16* src =
            (pl ? bql : bqh) + (size_t)(q0 + row) * QKV_F + h * HSZ + gr * 8;
        *(uint4*)&sp[pl][swz(row, gr)] = *(const uint4*)src;
    }
    __syncthreads();

    uint32_t qf_h[4][4], qf_l[4][4];
    {
        int row = warp_m + (lane & 7) + ((lane >> 3) & 1) * 8;
        #pragma unroll
        for (int ks = 0; ks < 4; ks++) {
            int gr = 2 * ks + (lane >> 4);
            ldsm_x4(qf_h[ks], smaddr(&sp[0][swz(row, gr)]));
            ldsm_x4(qf_l[ks], smaddr(&sp[1][swz(row, gr)]));
        }
    }
    __syncthreads();

    float m0v = -1e30f, m1v = -1e30f, l0 = 0.f, l1 = 0.f;
    float o[8][4];
    #pragma unroll
    for (int dt = 0; dt < 8; dt++)
        #pragma unroll
        for (int c = 0; c < 4; c++) o[dt][c] = 0.f;

    for (int kt = 0; kt < SEQ / 64; kt++) {
        const int k0 = kt * 64;
        // ---- load K/V hi/lo tiles ----
        #pragma unroll
        for (int i = 0; i < 16; i++) {
            int idx = i * 128 + tid;      // 0..2047
            int pl = idx >> 9;            // 0..3
            int rem = idx & 511;
            int row = rem >> 3, gr = rem & 7;
            const __nv_bfloat16* src = ((pl & 1) ? bql : bqh)
                + (size_t)(k0 + row) * QKV_F + HIDDEN + (pl >> 1) * HIDDEN
                + h * HSZ + gr * 8;
            *(uint4*)&sp[pl][swz(row, gr)] = *(const uint4*)src;
        }
        __syncthreads();

        // ---- S = Q K^T (scale pre-folded into Q) ----
        float s[8][4];
        #pragma unroll
        for (int nt = 0; nt < 8; nt++)
            #pragma unroll
            for (int c = 0; c < 4; c++) s[nt][c] = 0.f;

        #pragma unroll
        for (int ks = 0; ks < 4; ks++) {
            #pragma unroll
            for (int np = 0; np < 4; np++) {     // S-ntile pair 2np, 2np+1
                int row = 16 * np + (lane & 7) + (lane >> 4) * 8;
                int gr  = 2 * ks + ((lane >> 3) & 1);
                uint32_t kh[4], kl[4];
                ldsm_x4(kh, smaddr(&sp[0][swz(row, gr)]));
                ldsm_x4(kl, smaddr(&sp[1][swz(row, gr)]));
                mma_bf16(s[2 * np],     qf_h[ks], kh);
                mma_bf16(s[2 * np],     qf_h[ks], kl);
                mma_bf16(s[2 * np],     qf_l[ks], kh);
                mma_bf16(s[2 * np + 1], qf_h[ks], kh + 2);
                mma_bf16(s[2 * np + 1], qf_h[ks], kl + 2);
                mma_bf16(s[2 * np + 1], qf_l[ks], kh + 2);
            }
        }

        // ---- online softmax (rows g and g+8, state replicated over j lanes) ----
        float r0 = -1e30f, r1 = -1e30f;
        #pragma unroll
        for (int nt = 0; nt < 8; nt++) {
            r0 = fmaxf(r0, fmaxf(s[nt][0], s[nt][1]));
            r1 = fmaxf(r1, fmaxf(s[nt][2], s[nt][3]));
        }
        r0 = fmaxf(r0, __shfl_xor_sync(0xffffffffu, r0, 1));
        r0 = fmaxf(r0, __shfl_xor_sync(0xffffffffu, r0, 2));
        r1 = fmaxf(r1, __shfl_xor_sync(0xffffffffu, r1, 1));
        r1 = fmaxf(r1, __shfl_xor_sync(0xffffffffu, r1, 2));
        float mn0 = fmaxf(m0v, r0), mn1 = fmaxf(m1v, r1);
        float cor0 = __expf(m0v - mn0), cor1 = __expf(m1v - mn1);
        m0v = mn0; m1v = mn1;

        uint32_t ph[8][2], plo[8][2];
        float sum0 = 0.f, sum1 = 0.f;
        #pragma unroll
        for (int nt = 0; nt < 8; nt++) {
            float p0 = __expf(s[nt][0] - mn0), p1 = __expf(s[nt][1] - mn0);
            float p2 = __expf(s[nt][2] - mn1), p3 = __expf(s[nt][3] - mn1);
            sum0 += p0 + p1; sum1 += p2 + p3;
            __nv_bfloat162 hi01, lo01, hi23, lo23;
            split2(p0, p1, hi01, lo01);
            split2(p2, p3, hi23, lo23);
            ph[nt][0]  = *(uint32_t*)&hi01;  ph[nt][1]  = *(uint32_t*)&hi23;
            plo[nt][0] = *(uint32_t*)&lo01;  plo[nt][1] = *(uint32_t*)&lo23;
        }
        sum0 += __shfl_xor_sync(0xffffffffu, sum0, 1);
        sum0 += __shfl_xor_sync(0xffffffffu, sum0, 2);
        sum1 += __shfl_xor_sync(0xffffffffu, sum1, 1);
        sum1 += __shfl_xor_sync(0xffffffffu, sum1, 2);
        l0 = l0 * cor0 + sum0;
        l1 = l1 * cor1 + sum1;
        #pragma unroll
        for (int dt = 0; dt < 8; dt++) {
            o[dt][0] *= cor0; o[dt][1] *= cor0;
            o[dt][2] *= cor1; o[dt][3] *= cor1;
        }

        // ---- O += P V ----
        #pragma unroll
        for (int ks = 0; ks < 4; ks++) {
            uint32_t ah[4] = { ph[2 * ks][0],  ph[2 * ks][1],
                               ph[2 * ks + 1][0],  ph[2 * ks + 1][1] };
            uint32_t al[4] = { plo[2 * ks][0], plo[2 * ks][1],
                               plo[2 * ks + 1][0], plo[2 * ks + 1][1] };
            int row = 16 * ks + (lane & 7) + ((lane >> 3) & 1) * 8;
            #pragma unroll
            for (int dp = 0; dp < 4; dp++) {     // d-tile pair 2dp, 2dp+1
                int gr = 2 * dp + (lane >> 4);
                uint32_t vh[4], vl[4];
                ldsm_x4_t(vh, smaddr(&sp[2][swz(row, gr)]));
                ldsm_x4_t(vl, smaddr(&sp[3][swz(row, gr)]));
                mma_bf16(o[2 * dp],     ah, vh);
                mma_bf16(o[2 * dp],     ah, vl);
                mma_bf16(o[2 * dp],     al, vh);
                mma_bf16(o[2 * dp + 1], ah, vh + 2);
                mma_bf16(o[2 * dp + 1], ah, vl + 2);
                mma_bf16(o[2 * dp + 1], al, vh + 2);
            }
        }
        __syncthreads();
    }

    // ---- epilogue: normalize, write bf16 hi/lo for the output projection ----
    float inv0 = 1.f / l0, inv1 = 1.f / l1;
    int row0 = q0 + warp_m + g;
    size_t t0 = (size_t)(b * SEQ + row0) * HIDDEN + h * HSZ;
    size_t t1 = t0 + 8 * HIDDEN;
    #pragma unroll
    for (int dt = 0; dt < 8; dt++) {
        int col = dt * 8 + 2 * j;
        __nv_bfloat162 hi, lo;
        split2(o[dt][0] * inv0, o[dt][1] * inv0, hi, lo);
        *(__nv_bfloat162*)(ohi + t0 + col) = hi;
        *(__nv_bfloat162*)(olo + t0 + col) = lo;
        split2(o[dt][2] * inv1, o[dt][3] * inv1, hi, lo);
        *(__nv_bfloat162*)(ohi + t1 + col) = hi;
        *(__nv_bfloat162*)(olo + t1 + col) = lo;
    }
}

// ---------------------------------------------------------------------------
extern "C" void kernel_launch(void* const* d_in, const int* in_sizes, int n_in,
                              void* d_out, int out_size)
{
    const float* x    = (const float*)d_in[0];
    const float* Wqkv = (const float*)d_in[1];
    const float* bqkv = (const float*)d_in[2];
    const float* Wo   = (const float*)d_in[3];
    const float* bo   = (const float*)d_in[4];
    float* out = (float*)d_out;

    __nv_bfloat16 *xhi, *xlo, *wqh, *wql, *woh, *wol, *qkh, *qkl, *ahi, *alo;
    cudaGetSymbolAddress((void**)&xhi, g_xhi);
    cudaGetSymbolAddress((void**)&xlo, g_xlo);
    cudaGetSymbolAddress((void**)&wqh, g_wqt_hi);
    cudaGetSymbolAddress((void**)&wql, g_wqt_lo);
    cudaGetSymbolAddress((void**)&woh, g_wot_hi);
    cudaGetSymbolAddress((void**)&wol, g_wot_lo);
    cudaGetSymbolAddress((void**)&qkh, g_qkvh);
    cudaGetSymbolAddress((void**)&qkl, g_qkvl);
    cudaGetSymbolAddress((void**)&ahi, g_ahi);
    cudaGetSymbolAddress((void**)&alo, g_alo);

    // 0) inputs -> bf16 hi/lo
    {
        int n = MTOK * HIDDEN;
        f32_split_kernel<<<n / 4 / 256, 256>>>(x, xhi, xlo, n);
        transpose_split_kernel<<<dim3(QKV_F / 32, HIDDEN / 32), dim3(32, 8)>>>(
            Wqkv, wqh, wql, HIDDEN, QKV_F);
        transpose_split_kernel<<<dim3(HIDDEN / 32, HIDDEN / 32), dim3(32, 8)>>>(
            Wo, woh, wol, HIDDEN, HIDDEN);
    }
    // 1) QKV projection -> bf16 hi/lo qkv, Q pre-scaled by 1/sqrt(64)
    {
        dim3 grid(QKV_F / 128, MTOK / 128);
        gemm_mma_bf16out_kernel<<<grid, 256>>>(xhi, xlo, wqh, wql, bqkv,
                                               qkh, qkl, MTOK, QKV_F, HIDDEN,
                                               HIDDEN, 0.125f);
    }
    // 2) attention on HMMA -> bf16 hi/lo
    {
        dim3 grid(SEQ / 64, NHEAD, BATCH);
        attn_mma_kernel<<<grid, 128>>>(qkh, qkl, ahi, alo);
    }
    // 3) output projection -> fp32 out + bias
    {
        dim3 grid(HIDDEN / 128, MTOK / 128);
        gemm_mma_f32_kernel<<<grid, 256>>>(ahi, alo, woh, wol, bo, out,
                                           MTOK, HIDDEN, HIDDEN);
    }
}

// round 10
// speedup vs baseline: 3.3108x; 1.0946x over previous
#include <cuda_runtime.h>
#include <cuda_bf16.h>
#include <cstdint>

#define HIDDEN   1024
#define NHEAD    16
#define HSZ      64
#define BATCH    2
#define SEQ      2048
#define MTOK     (BATCH * SEQ)         // 4096 token rows
#define QKV_F    (3 * HIDDEN)          // 3072

// ---------------------------------------------------------------------------
// Scratch (no cudaMalloc allowed)
// ---------------------------------------------------------------------------
__device__ __nv_bfloat16 g_xhi[MTOK * HIDDEN];
__device__ __nv_bfloat16 g_xlo[MTOK * HIDDEN];
__device__ __nv_bfloat16 g_wqt_hi[QKV_F * HIDDEN];   // Wqkv^T [3072,1024]
__device__ __nv_bfloat16 g_wqt_lo[QKV_F * HIDDEN];
__device__ __nv_bfloat16 g_wot_hi[HIDDEN * HIDDEN];  // Wo^T [1024,1024]
__device__ __nv_bfloat16 g_wot_lo[HIDDEN * HIDDEN];
__device__ __nv_bfloat16 g_qkvh[MTOK * QKV_F];       // qkv hi (Q pre-scaled)
__device__ __nv_bfloat16 g_qkvl[MTOK * QKV_F];       // qkv lo
__device__ __nv_bfloat16 g_ahi[MTOK * HIDDEN];       // attn out hi
__device__ __nv_bfloat16 g_alo[MTOK * HIDDEN];       // attn out lo

// ---------------------------------------------------------------------------
// mma.sync / ldmatrix / cp.async helpers (sm_80+ ISA; valid on base sm_103)
// ---------------------------------------------------------------------------
__device__ __forceinline__ void ldsm_x4(uint32_t* r, uint32_t addr) {
    asm volatile("ldmatrix.sync.aligned.m8n8.x4.shared.b16 {%0,%1,%2,%3}, [%4];"
                 : "=r"(r[0]), "=r"(r[1]), "=r"(r[2]), "=r"(r[3]) : "r"(addr));
}
__device__ __forceinline__ void ldsm_x4_t(uint32_t* r, uint32_t addr) {
    asm volatile("ldmatrix.sync.aligned.m8n8.x4.trans.shared.b16 {%0,%1,%2,%3}, [%4];"
                 : "=r"(r[0]), "=r"(r[1]), "=r"(r[2]), "=r"(r[3]) : "r"(addr));
}
__device__ __forceinline__ void ldsm_x2(uint32_t* r, uint32_t addr) {
    asm volatile("ldmatrix.sync.aligned.m8n8.x2.shared.b16 {%0,%1}, [%2];"
                 : "=r"(r[0]), "=r"(r[1]) : "r"(addr));
}
__device__ __forceinline__ void mma_bf16(float* c, const uint32_t* a, const uint32_t* b) {
    asm volatile(
        "mma.sync.aligned.m16n8k16.row.col.f32.bf16.bf16.f32 "
        "{%0,%1,%2,%3}, {%4,%5,%6,%7}, {%8,%9}, {%0,%1,%2,%3};"
        : "+f"(c[0]), "+f"(c[1]), "+f"(c[2]), "+f"(c[3])
        : "r"(a[0]), "r"(a[1]), "r"(a[2]), "r"(a[3]), "r"(b[0]), "r"(b[1]));
}
__device__ __forceinline__ uint32_t smaddr(const void* p) {
    return (uint32_t)__cvta_generic_to_shared(p);
}
__device__ __forceinline__ void cp16(uint32_t dst, const void* src) {
    asm volatile("cp.async.cg.shared.global [%0], [%1], 16;"
                 :: "r"(dst), "l"(src));
}
#define CP_COMMIT() asm volatile("cp.async.commit_group;" ::: "memory")
#define CP_WAIT(n)  asm volatile("cp.async.wait_group %0;" :: "n"(n) : "memory")

// split a pair of fp32 into bf16x2 hi and lo planes
__device__ __forceinline__ void split2(float a, float b,
                                       __nv_bfloat162& hi, __nv_bfloat162& lo) {
    __nv_bfloat16 ha = __float2bfloat16(a), hb = __float2bfloat16(b);
    hi = __nv_bfloat162(ha, hb);
    lo = __nv_bfloat162(__float2bfloat16(a - __bfloat162float(ha)),
                        __float2bfloat16(b - __bfloat162float(hb)));
}

// ---------------------------------------------------------------------------
// fp32 -> bf16 hi/lo split (elementwise, float4 vectorized)
// ---------------------------------------------------------------------------
__global__ __launch_bounds__(256) void f32_split_kernel(
    const float* __restrict__ in, __nv_bfloat16* __restrict__ hi,
    __nv_bfloat16* __restrict__ lo, int n)
{
    int i = (blockIdx.x * 256 + threadIdx.x) * 4;
    if (i >= n) return;
    float4 v = *(const float4*)(in + i);
    __nv_bfloat162 h01, l01, h23, l23;
    split2(v.x, v.y, h01, l01);
    split2(v.z, v.w, h23, l23);
    *(__nv_bfloat162*)(hi + i)     = h01;
    *(__nv_bfloat162*)(hi + i + 2) = h23;
    *(__nv_bfloat162*)(lo + i)     = l01;
    *(__nv_bfloat162*)(lo + i + 2) = l23;
}

// ---------------------------------------------------------------------------
// Transpose W[K,N] fp32 -> T_hi/T_lo[N,K] bf16 split. block (32,8), tile 32x32.
// ---------------------------------------------------------------------------
__global__ __launch_bounds__(256) void transpose_split_kernel(
    const float* __restrict__ W, __nv_bfloat16* __restrict__ Thi,
    __nv_bfloat16* __restrict__ Tlo, int K, int N)
{
    __shared__ float t[32][33];
    int n = blockIdx.x * 32 + threadIdx.x;
    int k0 = blockIdx.y * 32;
    #pragma unroll
    for (int i = threadIdx.y; i < 32; i += 8)
        t[i][threadIdx.x] = W[(size_t)(k0 + i) * N + n];
    __syncthreads();
    int k = k0 + threadIdx.x;
    int nb = blockIdx.x * 32;
    #pragma unroll
    for (int i = threadIdx.y; i < 32; i += 8) {
        float v = t[threadIdx.x][i];
        __nv_bfloat16 h = __float2bfloat16(v);
        Thi[(size_t)(nb + i) * K + k] = h;
        Tlo[(size_t)(nb + i) * K + k] = __float2bfloat16(v - __bfloat162float(h));
    }
}

// ---------------------------------------------------------------------------
// HMMA GEMM with 2-stage cp.async pipeline. 128x128 tile, BK=32, 256 threads.
// Dynamic smem: 2 stages x 4 planes x 128 rows x 80B = 81920 bytes.
// ---------------------------------------------------------------------------
#define GROWB   80                   // bytes per smem row (40 bf16)
#define PLANEB  (128 * GROWB)        // 10240
#define STAGEB  (4 * PLANEB)         // 40960
#define GEMM_SMEM (2 * STAGEB)       // 81920

#define GEMM_COPY_STAGE(sgbase, kk)                                            \
    do {                                                                       \
        _Pragma("unroll")                                                      \
        for (int i0 = 0; i0 < 512; i0 += 256) {                                \
            int i = i0 + tid;                                                  \
            int r = i >> 2;                                                    \
            int cb = (i & 3) * 16;                                             \
            uint32_t d = (sgbase) + r * GROWB + cb;                            \
            size_t ga = (size_t)(m0 + r) * K + (kk) + (i & 3) * 8;             \
            size_t gb = (size_t)(n0 + r) * K + (kk) + (i & 3) * 8;             \
            cp16(d + 0 * PLANEB, Ahi + ga);                                    \
            cp16(d + 1 * PLANEB, Alo + ga);                                    \
            cp16(d + 2 * PLANEB, Bhi + gb);                                    \
            cp16(d + 3 * PLANEB, Blo + gb);                                    \
        }                                                                      \
    } while (0)

#define GEMM_MAINLOOP                                                          \
    extern __shared__ char dynsm[];                                            \
    const uint32_t sbase = smaddr(dynsm);                                      \
    const int tid  = threadIdx.x;                                              \
    const int wid  = tid >> 5;                                                 \
    const int lane = tid & 31;                                                 \
    const int warp_m = (wid & 1) * 64;                                         \
    const int warp_n = (wid >> 1) * 32;                                        \
    const int m0 = blockIdx.y * 128;                                           \
    const int n0 = blockIdx.x * 128;                                           \
    float acc[4][4][4];                                                        \
    _Pragma("unroll")                                                          \
    for (int i = 0; i < 4; i++)                                                \
        _Pragma("unroll")                                                      \
        for (int j2 = 0; j2 < 4; j2++)                                         \
            _Pragma("unroll")                                                  \
            for (int c = 0; c < 4; c++) acc[i][j2][c] = 0.f;                   \
    const int a_r = lane & 15;                                                 \
    const int a_c = (lane >> 4) * 8;                                           \
    const int b_r = lane & 7;                                                  \
    const int b_c = ((lane >> 3) & 1) * 8;                                     \
    const int niter = K / 32;                                                  \
    GEMM_COPY_STAGE(sbase, 0);                                                 \
    CP_COMMIT();                                                               \
    for (int it = 0; it < niter; it++) {                                       \
        if (it + 1 < niter) {                                                  \
            GEMM_COPY_STAGE(sbase + ((it + 1) & 1) * STAGEB, (it + 1) * 32);   \
            CP_COMMIT();                                                       \
            CP_WAIT(1);                                                        \
        } else {                                                               \
            CP_WAIT(0);                                                        \
        }                                                                      \
        __syncthreads();                                                       \
        const uint32_t st = sbase + (it & 1) * STAGEB;                         \
        _Pragma("unroll")                                                      \
        for (int ks = 0; ks < 2; ks++) {                                       \
            const int kbb = ks * 32;   /* bytes: ks*16 elements */             \
            uint32_t ah[4][4], al[4][4], bh[4][2], bl[4][2];                   \
            _Pragma("unroll")                                                  \
            for (int mt = 0; mt < 4; mt++) {                                   \
                int row = warp_m + mt * 16 + a_r;                              \
                uint32_t ad = st + row * GROWB + kbb + a_c * 2;                \
                ldsm_x4(ah[mt], ad + 0 * PLANEB);                              \
                ldsm_x4(al[mt], ad + 1 * PLANEB);                              \
            }                                                                  \
            _Pragma("unroll")                                                  \
            for (int nt = 0; nt < 4; nt++) {                                   \
                int row = warp_n + nt * 8 + b_r;                               \
                uint32_t bd = st + row * GROWB + kbb + b_c * 2;                \
                ldsm_x2(bh[nt], bd + 2 * PLANEB);                              \
                ldsm_x2(bl[nt], bd + 3 * PLANEB);                              \
            }                                                                  \
            _Pragma("unroll")                                                  \
            for (int mt = 0; mt < 4; mt++)                                     \
                _Pragma("unroll")                                              \
                for (int nt = 0; nt < 4; nt++) {                               \
                    mma_bf16(acc[mt][nt], ah[mt], bh[nt]);                     \
                    mma_bf16(acc[mt][nt], ah[mt], bl[nt]);                     \
                    mma_bf16(acc[mt][nt], al[mt], bh[nt]);                     \
                }                                                              \
        }                                                                      \
        __syncthreads();                                                       \
    }                                                                          \
    const int g = lane >> 2;                                                   \
    const int q = (lane & 3) * 2;

// GEMM variant 1: fp32 output + bias (final projection)
__global__ __launch_bounds__(256) void gemm_mma_f32_kernel(
    const __nv_bfloat16* __restrict__ Ahi, const __nv_bfloat16* __restrict__ Alo,
    const __nv_bfloat16* __restrict__ Bhi, const __nv_bfloat16* __restrict__ Blo,
    const float* __restrict__ bias, float* __restrict__ C,
    int M, int N, int K)
{
    GEMM_MAINLOOP
    #pragma unroll
    for (int mt = 0; mt < 4; mt++) {
        #pragma unroll
        for (int nt = 0; nt < 4; nt++) {
            int row = m0 + warp_m + mt * 16 + g;
            int col = n0 + warp_n + nt * 8 + q;
            float b0 = bias[col], b1 = bias[col + 1];
            float* p0 = C + (size_t)row * N + col;
            p0[0] = acc[mt][nt][0] + b0;
            p0[1] = acc[mt][nt][1] + b1;
            float* p1 = C + (size_t)(row + 8) * N + col;
            p1[0] = acc[mt][nt][2] + b0;
            p1[1] = acc[mt][nt][3] + b1;
        }
    }
}

// GEMM variant 2: bf16 hi/lo output + bias, cols < qcols scaled (QKV projection)
__global__ __launch_bounds__(256) void gemm_mma_bf16out_kernel(
    const __nv_bfloat16* __restrict__ Ahi, const __nv_bfloat16* __restrict__ Alo,
    const __nv_bfloat16* __restrict__ Bhi, const __nv_bfloat16* __restrict__ Blo,
    const float* __restrict__ bias,
    __nv_bfloat16* __restrict__ Chi, __nv_bfloat16* __restrict__ Clo,
    int M, int N, int K, int qcols, float qscale)
{
    GEMM_MAINLOOP
    #pragma unroll
    for (int mt = 0; mt < 4; mt++) {
        #pragma unroll
        for (int nt = 0; nt < 4; nt++) {
            int row = m0 + warp_m + mt * 16 + g;
            int col = n0 + warp_n + nt * 8 + q;
            float b0 = bias[col], b1 = bias[col + 1];
            float v00 = acc[mt][nt][0] + b0, v01 = acc[mt][nt][1] + b1;
            float v10 = acc[mt][nt][2] + b0, v11 = acc[mt][nt][3] + b1;
            if (col < qcols) { v00 *= qscale; v01 *= qscale; v10 *= qscale; v11 *= qscale; }
            __nv_bfloat162 h, l;
            split2(v00, v01, h, l);
            *(__nv_bfloat162*)(Chi + (size_t)row * N + col) = h;
            *(__nv_bfloat162*)(Clo + (size_t)row * N + col) = l;
            split2(v10, v11, h, l);
            *(__nv_bfloat162*)(Chi + (size_t)(row + 8) * N + col) = h;
            *(__nv_bfloat162*)(Clo + (size_t)(row + 8) * N + col) = l;
        }
    }
}

// ---------------------------------------------------------------------------
// Flash attention on HMMA, hi/lo splits, 2-stage cp.async K/V pipeline.
// Grid (SEQ/64, NHEAD, BATCH), 128 threads (4 warps x m16 rows).
// Dynamic smem: 2 stages x 4 planes x 8192B = 65536 bytes.
// planes: 0=Khi 1=Klo 2=Vhi 3=Vlo  (stage 0 planes 0/1 reused for Q prologue)
// ---------------------------------------------------------------------------
#define APLANEB 8192
#define ASTAGEB (4 * APLANEB)
#define ATT_SMEM (2 * ASTAGEB)

__device__ __forceinline__ int swzb(int row, int gran) {
    return row * 128 + ((gran ^ (row & 7)) << 4);   // byte offset, 64x64 bf16 tile
}

__global__ __launch_bounds__(128, 3) void attn_mma_kernel(
    const __nv_bfloat16* __restrict__ qhi, const __nv_bfloat16* __restrict__ qlo,
    __nv_bfloat16* __restrict__ ohi, __nv_bfloat16* __restrict__ olo)
{
    extern __shared__ char dynsm[];
    const uint32_t sbase = smaddr(dynsm);

    const int tid  = threadIdx.x;
    const int wid  = tid >> 5;
    const int lane = tid & 31;
    const int g = lane >> 2, j = lane & 3;
    const int q0 = blockIdx.x * 64;
    const int h  = blockIdx.y;
    const int b  = blockIdx.z;
    const int warp_m = wid * 16;

    const __nv_bfloat16* bqh = qhi + (size_t)b * SEQ * QKV_F;
    const __nv_bfloat16* bql = qlo + (size_t)b * SEQ * QKV_F;

    // ---- prologue: Q tile (hi/lo) via cp.async into stage0 planes 0/1 ----
    #pragma unroll
    for (int i = 0; i < 8; i++) {
        int idx = i * 128 + tid;          // 0..1023
        int pl = idx >> 9;
        int rem = idx & 511;
        int row = rem >> 3, gr = rem & 7;
        const __nv_bfloat16* src =
            (pl ? bql : bqh) + (size_t)(q0 + row) * QKV_F + h * HSZ + gr * 8;
        cp16(sbase + pl * APLANEB + swzb(row, gr), src);
    }
    CP_COMMIT();
    CP_WAIT(0);
    __syncthreads();

    uint32_t qf_h[4][4], qf_l[4][4];
    {
        int row = warp_m + (lane & 7) + ((lane >> 3) & 1) * 8;
        #pragma unroll
        for (int ks = 0; ks < 4; ks++) {
            int gr = 2 * ks + (lane >> 4);
            ldsm_x4(qf_h[ks], sbase + 0 * APLANEB + swzb(row, gr));
            ldsm_x4(qf_l[ks], sbase + 1 * APLANEB + swzb(row, gr));
        }
    }
    __syncthreads();   // Q fully consumed before stage0 is reused for K/V

    // ---- prefetch K/V tile 0 into stage 0 ----
    #pragma unroll
    for (int i = 0; i < 16; i++) {
        int idx = i * 128 + tid;      // 0..2047
        int pl = idx >> 9;
        int rem = idx & 511;
        int row = rem >> 3, gr = rem & 7;
        const __nv_bfloat16* src = ((pl & 1) ? bql : bqh)
            + (size_t)row * QKV_F + HIDDEN + (pl >> 1) * HIDDEN + h * HSZ + gr * 8;
        cp16(sbase + pl * APLANEB + swzb(row, gr), src);
    }
    CP_COMMIT();

    float m0v = -1e30f, m1v = -1e30f, l0 = 0.f, l1 = 0.f;
    float o[8][4];
    #pragma unroll
    for (int dt = 0; dt < 8; dt++)
        #pragma unroll
        for (int c = 0; c < 4; c++) o[dt][c] = 0.f;

    const int nkt = SEQ / 64;
    for (int kt = 0; kt < nkt; kt++) {
        if (kt + 1 < nkt) {
            const uint32_t st2 = sbase + ((kt + 1) & 1) * ASTAGEB;
            const int k1 = (kt + 1) * 64;
            #pragma unroll
            for (int i = 0; i < 16; i++) {
                int idx = i * 128 + tid;
                int pl = idx >> 9;
                int rem = idx & 511;
                int row = rem >> 3, gr = rem & 7;
                const __nv_bfloat16* src = ((pl & 1) ? bql : bqh)
                    + (size_t)(k1 + row) * QKV_F + HIDDEN + (pl >> 1) * HIDDEN
                    + h * HSZ + gr * 8;
                cp16(st2 + pl * APLANEB + swzb(row, gr), src);
            }
            CP_COMMIT();
            CP_WAIT(1);
        } else {
            CP_WAIT(0);
        }
        __syncthreads();
        const uint32_t st = sbase + (kt & 1) * ASTAGEB;

        // ---- S = Q K^T (scale pre-folded into Q) ----
        float s[8][4];
        #pragma unroll
        for (int nt = 0; nt < 8; nt++)
            #pragma unroll
            for (int c = 0; c < 4; c++) s[nt][c] = 0.f;

        #pragma unroll
        for (int ks = 0; ks < 4; ks++) {
            #pragma unroll
            for (int np = 0; np < 4; np++) {
                int row = 16 * np + (lane & 7) + (lane >> 4) * 8;
                int gr  = 2 * ks + ((lane >> 3) & 1);
                uint32_t kh[4], kl[4];
                ldsm_x4(kh, st + 0 * APLANEB + swzb(row, gr));
                ldsm_x4(kl, st + 1 * APLANEB + swzb(row, gr));
                mma_bf16(s[2 * np],     qf_h[ks], kh);
                mma_bf16(s[2 * np],     qf_h[ks], kl);
                mma_bf16(s[2 * np],     qf_l[ks], kh);
                mma_bf16(s[2 * np + 1], qf_h[ks], kh + 2);
                mma_bf16(s[2 * np + 1], qf_h[ks], kl + 2);
                mma_bf16(s[2 * np + 1], qf_l[ks], kh + 2);
            }
        }

        // ---- online softmax (rows g, g+8; state replicated over j lanes) ----
        float r0 = -1e30f, r1 = -1e30f;
        #pragma unroll
        for (int nt = 0; nt < 8; nt++) {
            r0 = fmaxf(r0, fmaxf(s[nt][0], s[nt][1]));
            r1 = fmaxf(r1, fmaxf(s[nt][2], s[nt][3]));
        }
        r0 = fmaxf(r0, __shfl_xor_sync(0xffffffffu, r0, 1));
        r0 = fmaxf(r0, __shfl_xor_sync(0xffffffffu, r0, 2));
        r1 = fmaxf(r1, __shfl_xor_sync(0xffffffffu, r1, 1));
        r1 = fmaxf(r1, __shfl_xor_sync(0xffffffffu, r1, 2));
        float mn0 = fmaxf(m0v, r0), mn1 = fmaxf(m1v, r1);
        float cor0 = __expf(m0v - mn0), cor1 = __expf(m1v - mn1);
        m0v = mn0; m1v = mn1;

        uint32_t ph[8][2], plo[8][2];
        float sum0 = 0.f, sum1 = 0.f;
        #pragma unroll
        for (int nt = 0; nt < 8; nt++) {
            float p0 = __expf(s[nt][0] - mn0), p1 = __expf(s[nt][1] - mn0);
            float p2 = __expf(s[nt][2] - mn1), p3 = __expf(s[nt][3] - mn1);
            sum0 += p0 + p1; sum1 += p2 + p3;
            __nv_bfloat162 hi01, lo01, hi23, lo23;
            split2(p0, p1, hi01, lo01);
            split2(p2, p3, hi23, lo23);
            ph[nt][0]  = *(uint32_t*)&hi01;  ph[nt][1]  = *(uint32_t*)&hi23;
            plo[nt][0] = *(uint32_t*)&lo01;  plo[nt][1] = *(uint32_t*)&lo23;
        }
        sum0 += __shfl_xor_sync(0xffffffffu, sum0, 1);
        sum0 += __shfl_xor_sync(0xffffffffu, sum0, 2);
        sum1 += __shfl_xor_sync(0xffffffffu, sum1, 1);
        sum1 += __shfl_xor_sync(0xffffffffu, sum1, 2);
        l0 = l0 * cor0 + sum0;
        l1 = l1 * cor1 + sum1;
        #pragma unroll
        for (int dt = 0; dt < 8; dt++) {
            o[dt][0] *= cor0; o[dt][1] *= cor0;
            o[dt][2] *= cor1; o[dt][3] *= cor1;
        }

        // ---- O += P V ----
        #pragma unroll
        for (int ks = 0; ks < 4; ks++) {
            uint32_t ah[4] = { ph[2 * ks][0],  ph[2 * ks][1],
                               ph[2 * ks + 1][0],  ph[2 * ks + 1][1] };
            uint32_t al[4] = { plo[2 * ks][0], plo[2 * ks][1],
                               plo[2 * ks + 1][0], plo[2 * ks + 1][1] };
            int row = 16 * ks + (lane & 7) + ((lane >> 3) & 1) * 8;
            #pragma unroll
            for (int dp = 0; dp < 4; dp++) {
                int gr = 2 * dp + (lane >> 4);
                uint32_t vh[4], vl[4];
                ldsm_x4_t(vh, st + 2 * APLANEB + swzb(row, gr));
                ldsm_x4_t(vl, st + 3 * APLANEB + swzb(row, gr));
                mma_bf16(o[2 * dp],     ah, vh);
                mma_bf16(o[2 * dp],     ah, vl);
                mma_bf16(o[2 * dp],     al, vh);
                mma_bf16(o[2 * dp + 1], ah, vh + 2);
                mma_bf16(o[2 * dp + 1], ah, vl + 2);
                mma_bf16(o[2 * dp + 1], al, vh + 2);
            }
        }
        __syncthreads();
    }

    // ---- epilogue: normalize, write bf16 hi/lo for the output projection ----
    float inv0 = 1.f / l0, inv1 = 1.f / l1;
    int row0 = q0 + warp_m + g;
    size_t t0 = (size_t)(b * SEQ + row0) * HIDDEN + h * HSZ;
    size_t t1 = t0 + 8 * HIDDEN;
    #pragma unroll
    for (int dt = 0; dt < 8; dt++) {
        int col = dt * 8 + 2 * j;
        __nv_bfloat162 hi, lo;
        split2(o[dt][0] * inv0, o[dt][1] * inv0, hi, lo);
        *(__nv_bfloat162*)(ohi + t0 + col) = hi;
        *(__nv_bfloat162*)(olo + t0 + col) = lo;
        split2(o[dt][2] * inv1, o[dt][3] * inv1, hi, lo);
        *(__nv_bfloat162*)(ohi + t1 + col) = hi;
        *(__nv_bfloat162*)(olo + t1 + col) = lo;
    }
}

// ---------------------------------------------------------------------------
extern "C" void kernel_launch(void* const* d_in, const int* in_sizes, int n_in,
                              void* d_out, int out_size)
{
    const float* x    = (const float*)d_in[0];
    const float* Wqkv = (const float*)d_in[1];
    const float* bqkv = (const float*)d_in[2];
    const float* Wo   = (const float*)d_in[3];
    const float* bo   = (const float*)d_in[4];
    float* out = (float*)d_out;

    __nv_bfloat16 *xhi, *xlo, *wqh, *wql, *woh, *wol, *qkh, *qkl, *ahi, *alo;
    cudaGetSymbolAddress((void**)&xhi, g_xhi);
    cudaGetSymbolAddress((void**)&xlo, g_xlo);
    cudaGetSymbolAddress((void**)&wqh, g_wqt_hi);
    cudaGetSymbolAddress((void**)&wql, g_wqt_lo);
    cudaGetSymbolAddress((void**)&woh, g_wot_hi);
    cudaGetSymbolAddress((void**)&wol, g_wot_lo);
    cudaGetSymbolAddress((void**)&qkh, g_qkvh);
    cudaGetSymbolAddress((void**)&qkl, g_qkvl);
    cudaGetSymbolAddress((void**)&ahi, g_ahi);
    cudaGetSymbolAddress((void**)&alo, g_alo);

    cudaFuncSetAttribute(gemm_mma_bf16out_kernel,
                         cudaFuncAttributeMaxDynamicSharedMemorySize, GEMM_SMEM);
    cudaFuncSetAttribute(gemm_mma_f32_kernel,
                         cudaFuncAttributeMaxDynamicSharedMemorySize, GEMM_SMEM);
    cudaFuncSetAttribute(attn_mma_kernel,
                         cudaFuncAttributeMaxDynamicSharedMemorySize, ATT_SMEM);

    // 0) inputs -> bf16 hi/lo
    {
        int n = MTOK * HIDDEN;
        f32_split_kernel<<<n / 4 / 256, 256>>>(x, xhi, xlo, n);
        transpose_split_kernel<<<dim3(QKV_F / 32, HIDDEN / 32), dim3(32, 8)>>>(
            Wqkv, wqh, wql, HIDDEN, QKV_F);
        transpose_split_kernel<<<dim3(HIDDEN / 32, HIDDEN / 32), dim3(32, 8)>>>(
            Wo, woh, wol, HIDDEN, HIDDEN);
    }
    // 1) QKV projection -> bf16 hi/lo qkv, Q pre-scaled by 1/sqrt(64)
    {
        dim3 grid(QKV_F / 128, MTOK / 128);
        gemm_mma_bf16out_kernel<<<grid, 256, GEMM_SMEM>>>(
            xhi, xlo, wqh, wql, bqkv, qkh, qkl, MTOK, QKV_F, HIDDEN,
            HIDDEN, 0.125f);
    }
    // 2) attention on HMMA -> bf16 hi/lo
    {
        dim3 grid(SEQ / 64, NHEAD, BATCH);
        attn_mma_kernel<<<grid, 128, ATT_SMEM>>>(qkh, qkl, ahi, alo);
    }
    // 3) output projection -> fp32 out + bias
    {
        dim3 grid(HIDDEN / 128, MTOK / 128);
        gemm_mma_f32_kernel<<<grid, 256, GEMM_SMEM>>>(
            ahi, alo, woh, wol, bo, out, MTOK, HIDDEN, HIDDEN);
    }
}